// round 2
// baseline (speedup 1.0000x reference)
#include <cuda_runtime.h>
#include <cstdint>

#define Bb 8
#define Nn 2048

// ---------------- scratch (static device memory; no allocations) ----------------
__device__ float g_A1[256 * 256];
__device__ float g_A2[256 * 256];
__device__ float g_M1[256 * 256];
__device__ float g_M2[256 * 256];
__device__ float g_cpart[2][256];
__device__ float g_u[4][256];
__device__ float g_C[2];
__device__ float g_V1[Bb * Nn * 256];
__device__ float g_V2[Bb * Nn * 256];
__device__ float g_sq1[Bb * Nn];
__device__ float g_sk1[Bb * Nn];
__device__ float g_sq2[Bb * Nn];
__device__ float g_sk2[Bb * Nn];

// ---------------- packed fp32x2 helpers (sm_103a) ----------------
__device__ __forceinline__ unsigned long long pack2(float x) {
    unsigned long long r;
    asm("mov.b64 %0, {%1, %1};" : "=l"(r) : "f"(x));
    return r;
}
__device__ __forceinline__ void fma2(unsigned long long& d, unsigned long long a,
                                     unsigned long long b) {
    asm("fma.rn.f32x2 %0, %1, %2, %0;" : "+l"(d) : "l"(a), "l"(b));
}
__device__ __forceinline__ float2 unpack2(unsigned long long v) {
    float2 f;
    asm("mov.b64 {%0, %1}, %2;" : "=f"(f.x), "=f"(f.y) : "l"(v));
    return f;
}

// ---------------- weight folding: u-vectors + scalar consts ----------------
__global__ void k_fold_u(const float* __restrict__ qw, const float* __restrict__ qb,
                         const float* __restrict__ kvw, const float* __restrict__ kvb,
                         const float* __restrict__ osw, const float* __restrict__ osb,
                         const float* __restrict__ saw, const float* __restrict__ sab,
                         const float* __restrict__ ssw, const float* __restrict__ ssb) {
    int i = threadIdx.x;
    float a = 0.f, b = 0.f, c = 0.f, d = 0.f;
    for (int h = 0; h < 256; h++) {
        a += qw[h * 256 + i] * osw[h];
        b += kvw[h * 256 + i] * osw[256 + h];
        c += saw[h * 256 + i] * ssw[h];
        d += saw[(256 + h) * 256 + i] * ssw[256 + h];
    }
    g_u[0][i] = a; g_u[1][i] = b; g_u[2][i] = c; g_u[3][i] = d;
    if (i == 0) {
        float C1 = osb[0], C2 = ssb[0];
        for (int h = 0; h < 256; h++) {
            C1 += qb[h] * osw[h] + kvb[h] * osw[256 + h];
            C2 += sab[h] * ssw[h] + sab[256 + h] * ssw[256 + h];
        }
        g_C[0] = C1; g_C[1] = C2;
    }
}

// A1[h][j] = sum_d oma_o_w[d][h] * mix_w[j][d]        (y=0)
// A2[h][j] = sum_d sa_o_w[d][h]  * mix_w[j][256+d]    (y=1)
__global__ void k_fold_A(const float* __restrict__ ow, const float* __restrict__ sow,
                         const float* __restrict__ mixw) {
    int j = blockIdx.x, y = blockIdx.y, h = threadIdx.x;
    const float* W = y ? sow : ow;
    const float* mrow = mixw + j * 512 + y * 256;
    float s = 0.f;
    for (int d = 0; d < 256; d++) s += W[d * 256 + h] * mrow[d];
    (y ? g_A2 : g_A1)[h * 256 + j] = s;
}

// M[i][j] = sum_h Wv[h][i] * A[h][j] ; const partials via block reduce
__global__ void k_fold_M(const float* __restrict__ kvw, const float* __restrict__ kvb,
                         const float* __restrict__ saw, const float* __restrict__ sab,
                         const float* __restrict__ ob1, const float* __restrict__ ob2,
                         const float* __restrict__ mixw) {
    int j = blockIdx.x, y = blockIdx.y, i = threadIdx.x;
    const float* W = y ? (saw + 512 * 256) : (kvw + 256 * 256);
    const float* A = y ? g_A2 : g_A1;
    const float* bb = y ? (sab + 512) : (kvb + 256);
    const float* ob = y ? ob2 : ob1;
    float s = 0.f;
    for (int h = 0; h < 256; h++) s += W[h * 256 + i] * A[h * 256 + j];
    (y ? g_M2 : g_M1)[i * 256 + j] = s;

    __shared__ float red[256];
    red[i] = bb[i] * A[i * 256 + j] + ob[i] * mixw[j * 512 + y * 256 + i];
    __syncthreads();
    for (int st = 128; st > 0; st >>= 1) {
        if (i < st) red[i] += red[i + st];
        __syncthreads();
    }
    if (i == 0) g_cpart[y][j] = red[0];
}

// per-row score scalars: y=0 sq1(machine,uq1,+C1) y=1 sk1(op,uk1) y=2 sq2(machine,+C2) y=3 sk2(machine)
__global__ void k_sqk(const float* __restrict__ opf, const float* __restrict__ mf) {
    int y = blockIdx.y;
    int row = blockIdx.x * 8 + (threadIdx.x >> 5);
    int l = threadIdx.x & 31;
    const float* X = (y == 1) ? opf : mf;
    const float* u = g_u[y];
    const float* xr = X + (size_t)row * 256;
    float s = 0.f;
#pragma unroll
    for (int t = 0; t < 8; t++) s += xr[t * 32 + l] * u[t * 32 + l];
#pragma unroll
    for (int o = 16; o > 0; o >>= 1) s += __shfl_xor_sync(0xffffffffu, s, o);
    if (l == 0) {
        float add = (y == 0) ? g_C[0] : (y == 2) ? g_C[1] : 0.f;
        float* dst = (y == 0) ? g_sq1 : (y == 1) ? g_sk1 : (y == 2) ? g_sq2 : g_sk2;
        dst[row] = s + add;
    }
}

// V' = X @ M : (16384 x 256) @ (256 x 256), packed f32x2 inner loop
__global__ void __launch_bounds__(256, 2)
k_proj(const float* __restrict__ opf, const float* __restrict__ mf) {
    int y = blockIdx.y;
    const float* X = y ? mf : opf;
    const float* M = y ? g_M2 : g_M1;
    float* V = y ? g_V2 : g_V1;
    int r0 = blockIdx.x * 64;
    int j = threadIdx.x;
    __shared__ __align__(16) float Xt[32][68];

    unsigned long long acc[32];
#pragma unroll
    for (int p = 0; p < 32; p++) acc[p] = 0ull;

    for (int k0 = 0; k0 < 256; k0 += 32) {
        __syncthreads();
#pragma unroll
        for (int p = 0; p < 8; p++) {
            int idx = p * 256 + j;
            int k = idx & 31, r = idx >> 5;
            Xt[k][r] = X[(size_t)(r0 + r) * 256 + k0 + k];
        }
        __syncthreads();
#pragma unroll 4
        for (int k = 0; k < 32; k++) {
            float mv = __ldg(&M[(k0 + k) * 256 + j]);
            unsigned long long mp = pack2(mv);
            const ulonglong2* rowp = (const ulonglong2*)&Xt[k][0];
#pragma unroll
            for (int q = 0; q < 16; q++) {
                ulonglong2 ww = rowp[q];
                fma2(acc[2 * q], ww.x, mp);
                fma2(acc[2 * q + 1], ww.y, mp);
            }
        }
    }
#pragma unroll
    for (int p = 0; p < 32; p++) {
        float2 v = unpack2(acc[p]);
        V[(size_t)(r0 + 2 * p) * 256 + j] = v.x;
        V[(size_t)(r0 + 2 * p + 1) * 256 + j] = v.y;
    }
}

// main fused dual-attention: per block 32 rows x 256 cols, stream over c.
// w = exp(leaky(sq[m]+sk[c]) * mask[m,c]); out = (sum_c w*V')/D + cvec
__global__ void __launch_bounds__(256, 2)
k_main(const float* __restrict__ mask1, const float* __restrict__ mask2,
       const float* __restrict__ mixb, float* __restrict__ out) {
    int b = blockIdx.y, m0 = blockIdx.x * 32;
    int tid = threadIdx.x, w = tid >> 5, l = tid & 31, j = tid;
    __shared__ __align__(16) float Wt1[32][36];
    __shared__ __align__(16) float Wt2[32][36];
    __shared__ float sqs1[32], sqs2[32], sDi1[32], sDi2[32];

    if (tid < 32) sqs1[tid] = g_sq1[b * Nn + m0 + tid];
    else if (tid < 64) sqs2[tid - 32] = g_sq2[b * Nn + m0 + tid - 32];
    float cv = g_cpart[0][j] + g_cpart[1][j] + mixb[j];

    unsigned long long acc1[16], acc2[16];
#pragma unroll
    for (int p = 0; p < 16; p++) { acc1[p] = 0ull; acc2[p] = 0ull; }
    float d1[4] = {0.f, 0.f, 0.f, 0.f}, d2[4] = {0.f, 0.f, 0.f, 0.f};

    const float* V1b = g_V1 + (size_t)b * Nn * 256;
    const float* V2b = g_V2 + (size_t)b * Nn * 256;
    const float* sk1b = g_sk1 + b * Nn;
    const float* sk2b = g_sk2 + b * Nn;
    const float* m1b = mask1 + ((size_t)b * Nn + m0) * Nn;
    const float* m2b = mask2 + ((size_t)b * Nn + m0) * Nn;
    __syncthreads();

    for (int c0 = 0; c0 < Nn; c0 += 32) {
        // ---- phase A: score tile (warp w, lane l) -> Wt[c_local][m] ----
        int c = c0 + l;
        float sk1v = sk1b[c], sk2v = sk2b[c];
#pragma unroll
        for (int k = 0; k < 4; k++) {
            int m = 8 * k + w;
            float mk1 = __ldg(&m1b[(size_t)m * Nn + c]);
            float s = sqs1[m] + sk1v;
            s = s > 0.f ? s : 0.01f * s;
            float e1 = __expf(s * mk1);
            Wt1[l][m] = e1; d1[k] += e1;

            float mk2 = __ldg(&m2b[(size_t)m * Nn + c]);
            float t = sqs2[m] + sk2v;
            t = t > 0.f ? t : 0.01f * t;
            float e2 = __expf(t * mk2);
            Wt2[l][m] = e2; d2[k] += e2;
        }
        __syncthreads();

        // ---- phase B: packed f32x2 rank-update ----
#pragma unroll 2
        for (int cc = 0; cc < 32; cc += 4) {
            float v1r[4], v2r[4];
#pragma unroll
            for (int i = 0; i < 4; i++) {
                v1r[i] = __ldg(&V1b[(size_t)(c0 + cc + i) * 256 + j]);
                v2r[i] = __ldg(&V2b[(size_t)(c0 + cc + i) * 256 + j]);
            }
#pragma unroll
            for (int i = 0; i < 4; i++) {
                unsigned long long vp1 = pack2(v1r[i]);
                unsigned long long vp2 = pack2(v2r[i]);
                const ulonglong2* r1 = (const ulonglong2*)&Wt1[cc + i][0];
                const ulonglong2* r2 = (const ulonglong2*)&Wt2[cc + i][0];
#pragma unroll
                for (int q = 0; q < 8; q++) {
                    ulonglong2 wa = r1[q];
                    fma2(acc1[2 * q], wa.x, vp1);
                    fma2(acc1[2 * q + 1], wa.y, vp1);
                    ulonglong2 wb = r2[q];
                    fma2(acc2[2 * q], wb.x, vp2);
                    fma2(acc2[2 * q + 1], wb.y, vp2);
                }
            }
        }
        __syncthreads();
    }

    // ---- denominators: lane l accumulated disjoint c -> warp reduce ----
#pragma unroll
    for (int k = 0; k < 4; k++) {
        float v = d1[k];
#pragma unroll
        for (int o = 16; o > 0; o >>= 1) v += __shfl_xor_sync(0xffffffffu, v, o);
        if (l == 0) sDi1[8 * k + w] = v;
        float v2 = d2[k];
#pragma unroll
        for (int o = 16; o > 0; o >>= 1) v2 += __shfl_xor_sync(0xffffffffu, v2, o);
        if (l == 0) sDi2[8 * k + w] = v2;
    }
    __syncthreads();
    if (tid < 32) sDi1[tid] = 1.0f / sDi1[tid];
    else if (tid < 64) sDi2[tid - 32] = 1.0f / sDi2[tid - 32];
    __syncthreads();

    float* outb = out + ((size_t)b * Nn + m0) * 256;
#pragma unroll
    for (int p = 0; p < 16; p++) {
        float2 a1 = unpack2(acc1[p]);
        float2 a2 = unpack2(acc2[p]);
        int m = 2 * p;
        outb[(size_t)m * 256 + j] = a1.x * sDi1[m] + a2.x * sDi2[m] + cv;
        outb[(size_t)(m + 1) * 256 + j] = a1.y * sDi1[m + 1] + a2.y * sDi2[m + 1] + cv;
    }
}

// ---------------- launch ----------------
extern "C" void kernel_launch(void* const* d_in, const int* in_sizes, int n_in,
                              void* d_out, int out_size) {
    const float* opf  = (const float*)d_in[0];
    const float* mf   = (const float*)d_in[1];
    const float* tmask = (const float*)d_in[2];
    const float* smask = (const float*)d_in[3];
    const float* qw  = (const float*)d_in[4];
    const float* qb  = (const float*)d_in[5];
    const float* kvw = (const float*)d_in[6];
    const float* kvb = (const float*)d_in[7];
    const float* osw = (const float*)d_in[8];
    const float* osb = (const float*)d_in[9];
    const float* ow  = (const float*)d_in[10];
    const float* ob  = (const float*)d_in[11];
    const float* saw = (const float*)d_in[12];
    const float* sab = (const float*)d_in[13];
    const float* ssw = (const float*)d_in[14];
    const float* ssb = (const float*)d_in[15];
    const float* sow = (const float*)d_in[16];
    const float* sob = (const float*)d_in[17];
    const float* mixw = (const float*)d_in[18];
    const float* mixb = (const float*)d_in[19];
    float* out = (float*)d_out;

    k_fold_u<<<1, 256>>>(qw, qb, kvw, kvb, osw, osb, saw, sab, ssw, ssb);
    k_fold_A<<<dim3(256, 2), 256>>>(ow, sow, mixw);
    k_fold_M<<<dim3(256, 2), 256>>>(kvw, kvb, saw, sab, ob, sob, mixw);
    k_sqk<<<dim3(2048, 4), 256>>>(opf, mf);
    k_proj<<<dim3(256, 2), 256>>>(opf, mf);
    k_main<<<dim3(64, 8), 256>>>(tmask, smask, mixb, out);
}

// round 3
// speedup vs baseline: 1.0690x; 1.0690x over previous
#include <cuda_runtime.h>
#include <cstdint>

#define Bb 8
#define Nn 2048

// ---------------- scratch (static device memory; no allocations) ----------------
__device__ float g_A1[256 * 256];
__device__ float g_A2[256 * 256];
__device__ float g_M1[256 * 256];
__device__ float g_M2[256 * 256];
__device__ float g_cpart[2][256];
__device__ float g_u[4][256];
__device__ float g_C[2];
__device__ float g_V1[Bb * Nn * 256];
__device__ float g_V2[Bb * Nn * 256];
__device__ float g_sq1[Bb * Nn];
__device__ float g_sk1[Bb * Nn];
__device__ float g_sq2[Bb * Nn];
__device__ float g_sk2[Bb * Nn];

// ---------------- packed fp32x2 helpers (sm_103a) ----------------
__device__ __forceinline__ unsigned long long pack2(float x) {
    unsigned long long r;
    asm("mov.b64 %0, {%1, %1};" : "=l"(r) : "f"(x));
    return r;
}
__device__ __forceinline__ void fma2(unsigned long long& d, unsigned long long a,
                                     unsigned long long b) {
    asm("fma.rn.f32x2 %0, %1, %2, %0;" : "+l"(d) : "l"(a), "l"(b));
}
__device__ __forceinline__ float2 unpack2(unsigned long long v) {
    float2 f;
    asm("mov.b64 {%0, %1}, %2;" : "=f"(f.x), "=f"(f.y) : "l"(v));
    return f;
}

// ---------------- weight folding: u-vectors + scalar consts ----------------
__global__ void k_fold_u(const float* __restrict__ qw, const float* __restrict__ qb,
                         const float* __restrict__ kvw, const float* __restrict__ kvb,
                         const float* __restrict__ osw, const float* __restrict__ osb,
                         const float* __restrict__ saw, const float* __restrict__ sab,
                         const float* __restrict__ ssw, const float* __restrict__ ssb) {
    int i = threadIdx.x;
    float a = 0.f, b = 0.f, c = 0.f, d = 0.f;
    for (int h = 0; h < 256; h++) {
        a += qw[h * 256 + i] * osw[h];
        b += kvw[h * 256 + i] * osw[256 + h];
        c += saw[h * 256 + i] * ssw[h];
        d += saw[(256 + h) * 256 + i] * ssw[256 + h];
    }
    g_u[0][i] = a; g_u[1][i] = b; g_u[2][i] = c; g_u[3][i] = d;
    if (i == 0) {
        float C1 = osb[0], C2 = ssb[0];
        for (int h = 0; h < 256; h++) {
            C1 += qb[h] * osw[h] + kvb[h] * osw[256 + h];
            C2 += sab[h] * ssw[h] + sab[256 + h] * ssw[256 + h];
        }
        g_C[0] = C1; g_C[1] = C2;
    }
}

// A1[h][j] = sum_d oma_o_w[d][h] * mix_w[j][d]        (y=0)
// A2[h][j] = sum_d sa_o_w[d][h]  * mix_w[j][256+d]    (y=1)
__global__ void k_fold_A(const float* __restrict__ ow, const float* __restrict__ sow,
                         const float* __restrict__ mixw) {
    int j = blockIdx.x, y = blockIdx.y, h = threadIdx.x;
    const float* W = y ? sow : ow;
    const float* mrow = mixw + j * 512 + y * 256;
    float s = 0.f;
    for (int d = 0; d < 256; d++) s += W[d * 256 + h] * mrow[d];
    (y ? g_A2 : g_A1)[h * 256 + j] = s;
}

// M[i][j] = sum_h Wv[h][i] * A[h][j] ; const partials via block reduce
__global__ void k_fold_M(const float* __restrict__ kvw, const float* __restrict__ kvb,
                         const float* __restrict__ saw, const float* __restrict__ sab,
                         const float* __restrict__ ob1, const float* __restrict__ ob2,
                         const float* __restrict__ mixw) {
    int j = blockIdx.x, y = blockIdx.y, i = threadIdx.x;
    const float* W = y ? (saw + 512 * 256) : (kvw + 256 * 256);
    const float* A = y ? g_A2 : g_A1;
    const float* bb = y ? (sab + 512) : (kvb + 256);
    const float* ob = y ? ob2 : ob1;
    float s = 0.f;
    for (int h = 0; h < 256; h++) s += W[h * 256 + i] * A[h * 256 + j];
    (y ? g_M2 : g_M1)[i * 256 + j] = s;

    __shared__ float red[256];
    red[i] = bb[i] * A[i * 256 + j] + ob[i] * mixw[j * 512 + y * 256 + i];
    __syncthreads();
    for (int st = 128; st > 0; st >>= 1) {
        if (i < st) red[i] += red[i + st];
        __syncthreads();
    }
    if (i == 0) g_cpart[y][j] = red[0];
}

// per-row score scalars
__global__ void k_sqk(const float* __restrict__ opf, const float* __restrict__ mf) {
    int y = blockIdx.y;
    int row = blockIdx.x * 8 + (threadIdx.x >> 5);
    int l = threadIdx.x & 31;
    const float* X = (y == 1) ? opf : mf;
    const float* u = g_u[y];
    const float* xr = X + (size_t)row * 256;
    float s = 0.f;
#pragma unroll
    for (int t = 0; t < 8; t++) s += xr[t * 32 + l] * u[t * 32 + l];
#pragma unroll
    for (int o = 16; o > 0; o >>= 1) s += __shfl_xor_sync(0xffffffffu, s, o);
    if (l == 0) {
        float add = (y == 0) ? g_C[0] : (y == 2) ? g_C[1] : 0.f;
        float* dst = (y == 0) ? g_sq1 : (y == 1) ? g_sk1 : (y == 2) ? g_sq2 : g_sk2;
        dst[row] = s + add;
    }
}

// V' = X @ M : (16384 x 256) @ (256 x 256), packed f32x2 inner loop
__global__ void __launch_bounds__(256, 2)
k_proj(const float* __restrict__ opf, const float* __restrict__ mf) {
    int y = blockIdx.y;
    const float* X = y ? mf : opf;
    const float* M = y ? g_M2 : g_M1;
    float* V = y ? g_V2 : g_V1;
    int r0 = blockIdx.x * 64;
    int j = threadIdx.x;
    __shared__ __align__(16) float Xt[32][68];

    unsigned long long acc[32];
#pragma unroll
    for (int p = 0; p < 32; p++) acc[p] = 0ull;

    for (int k0 = 0; k0 < 256; k0 += 32) {
        __syncthreads();
#pragma unroll
        for (int p = 0; p < 8; p++) {
            int idx = p * 256 + j;
            int k = idx & 31, r = idx >> 5;
            Xt[k][r] = X[(size_t)(r0 + r) * 256 + k0 + k];
        }
        __syncthreads();
#pragma unroll 4
        for (int k = 0; k < 32; k++) {
            float mv = __ldg(&M[(k0 + k) * 256 + j]);
            unsigned long long mp = pack2(mv);
            const ulonglong2* rowp = (const ulonglong2*)&Xt[k][0];
#pragma unroll
            for (int q = 0; q < 16; q++) {
                ulonglong2 ww = rowp[q];
                fma2(acc[2 * q], ww.x, mp);
                fma2(acc[2 * q + 1], ww.y, mp);
            }
        }
    }
#pragma unroll
    for (int p = 0; p < 32; p++) {
        float2 v = unpack2(acc[p]);
        V[(size_t)(r0 + 2 * p) * 256 + j] = v.x;
        V[(size_t)(r0 + 2 * p + 1) * 256 + j] = v.y;
    }
}

// ---------------- single-attention pass: 64 m-rows x 256 j per block ----------------
// PASS 0: out = (P1 @ V1') scaled + cv    PASS 1: out += (P2 @ V2') scaled
template <int PASS>
__global__ void __launch_bounds__(256, 2)
k_attn(const float* __restrict__ mask, const float* __restrict__ mixb,
       float* __restrict__ out) {
    int b = blockIdx.y, m0 = blockIdx.x * 64;
    int tid = threadIdx.x, w = tid >> 5, l = tid & 31, j = tid;

    const float* Vb  = (PASS ? g_V2 : g_V1) + (size_t)b * Nn * 256;
    const float* sqg = (PASS ? g_sq2 : g_sq1) + b * Nn + m0;
    const float* skb = (PASS ? g_sk2 : g_sk1) + b * Nn;
    const float* mb  = mask + ((size_t)b * Nn + m0) * Nn;

    __shared__ __align__(16) float Wt[32][68];   // [c_local][m]
    __shared__ float sqs[64], sDi[64];

    if (tid < 64) sqs[tid] = sqg[tid];

    unsigned long long acc[32];
#pragma unroll
    for (int p = 0; p < 32; p++) acc[p] = 0ull;
    float den[8];
#pragma unroll
    for (int k = 0; k < 8; k++) den[k] = 0.f;

    for (int c0 = 0; c0 < Nn; c0 += 32) {
        __syncthreads();
        // ---- phase A: score tile -> Wt[c][m], thread (w,l): c=c0+l, m=8k+w ----
        {
            int c = c0 + l;
            float skv = skb[c];
#pragma unroll
            for (int k = 0; k < 8; k++) {
                int m = 8 * k + w;
                float mk = __ldg(&mb[(size_t)m * Nn + c]);
                float s = sqs[m] + skv;
                s = s > 0.f ? s : 0.01f * s;
                float e = __expf(s * mk);
                Wt[l][m] = e;
                den[k] += e;
            }
        }
        __syncthreads();

        // ---- phase B: rank-32 update, packed f32x2 ----
#pragma unroll
        for (int cc = 0; cc < 32; cc += 8) {
            float v[8];
#pragma unroll
            for (int i = 0; i < 8; i++)
                v[i] = __ldg(&Vb[(size_t)(c0 + cc + i) * 256 + j]);
#pragma unroll
            for (int i = 0; i < 8; i++) {
                unsigned long long vp = pack2(v[i]);
                const ulonglong2* r = (const ulonglong2*)&Wt[cc + i][0];
#pragma unroll
                for (int q = 0; q < 16; q++) {
                    ulonglong2 ww = r[q];
                    fma2(acc[2 * q], ww.x, vp);
                    fma2(acc[2 * q + 1], ww.y, vp);
                }
            }
        }
    }

    // ---- denominators: lane-reduce each den[k] -> sDi[8k+w] ----
    __syncthreads();
#pragma unroll
    for (int k = 0; k < 8; k++) {
        float v = den[k];
#pragma unroll
        for (int o = 16; o > 0; o >>= 1) v += __shfl_xor_sync(0xffffffffu, v, o);
        if (l == 0) sDi[8 * k + w] = v;
    }
    __syncthreads();
    if (tid < 64) sDi[tid] = 1.0f / sDi[tid];
    __syncthreads();

    float* ob = out + ((size_t)b * Nn + m0) * 256 + j;
    if (PASS == 0) {
        float cv = g_cpart[0][j] + g_cpart[1][j] + mixb[j];
#pragma unroll
        for (int p = 0; p < 32; p++) {
            float2 a = unpack2(acc[p]);
            int m = 2 * p;
            ob[(size_t)m * 256] = a.x * sDi[m] + cv;
            ob[(size_t)(m + 1) * 256] = a.y * sDi[m + 1] + cv;
        }
    } else {
#pragma unroll
        for (int p = 0; p < 32; p++) {
            float2 a = unpack2(acc[p]);
            int m = 2 * p;
            ob[(size_t)m * 256] += a.x * sDi[m];
            ob[(size_t)(m + 1) * 256] += a.y * sDi[m + 1];
        }
    }
}

// ---------------- launch ----------------
extern "C" void kernel_launch(void* const* d_in, const int* in_sizes, int n_in,
                              void* d_out, int out_size) {
    const float* opf  = (const float*)d_in[0];
    const float* mf   = (const float*)d_in[1];
    const float* tmask = (const float*)d_in[2];
    const float* smask = (const float*)d_in[3];
    const float* qw  = (const float*)d_in[4];
    const float* qb  = (const float*)d_in[5];
    const float* kvw = (const float*)d_in[6];
    const float* kvb = (const float*)d_in[7];
    const float* osw = (const float*)d_in[8];
    const float* osb = (const float*)d_in[9];
    const float* ow  = (const float*)d_in[10];
    const float* ob  = (const float*)d_in[11];
    const float* saw = (const float*)d_in[12];
    const float* sab = (const float*)d_in[13];
    const float* ssw = (const float*)d_in[14];
    const float* ssb = (const float*)d_in[15];
    const float* sow = (const float*)d_in[16];
    const float* sob = (const float*)d_in[17];
    const float* mixw = (const float*)d_in[18];
    const float* mixb = (const float*)d_in[19];
    float* out = (float*)d_out;

    k_fold_u<<<1, 256>>>(qw, qb, kvw, kvb, osw, osb, saw, sab, ssw, ssb);
    k_fold_A<<<dim3(256, 2), 256>>>(ow, sow, mixw);
    k_fold_M<<<dim3(256, 2), 256>>>(kvw, kvb, saw, sab, ob, sob, mixw);
    k_sqk<<<dim3(2048, 4), 256>>>(opf, mf);
    k_proj<<<dim3(256, 2), 256>>>(opf, mf);
    k_attn<0><<<dim3(32, 8), 256>>>(tmask, mixb, out);
    k_attn<1><<<dim3(32, 8), 256>>>(smask, mixb, out);
}

// round 5
// speedup vs baseline: 2.2559x; 2.1103x over previous
#include <cuda_runtime.h>
#include <cuda_bf16.h>
#include <cstdint>

#define Bb 8
#define Nn 2048

// ---------------- scratch (static device memory; no allocations) ----------------
__device__ float g_A1[256 * 256];
__device__ float g_A2[256 * 256];
__device__ float g_M1[256 * 256];
__device__ float g_M2[256 * 256];
__device__ float g_cpart[2][256];
__device__ float g_u[4][256];
__device__ float g_C[2];
__device__ float g_sq1[Bb * Nn];
__device__ float g_sk1[Bb * Nn];
__device__ float g_sq2[Bb * Nn];
__device__ float g_sk2[Bb * Nn];
// Pre-swizzled bf16 tile images: [pass][b][chunk] of 32KB (256 j-rows x 64 c bf16,
// row = j (128B), 16B-groups XOR-permuted by (j&7))
__device__ __align__(256) char g_Bhi[2 * 8 * 32 * 32768];
__device__ __align__(256) char g_Blo[2 * 8 * 32 * 32768];

// ---------------- packed fp32x2 helpers (k_proj compute) ----------------
__device__ __forceinline__ unsigned long long pack2(float x) {
    unsigned long long r;
    asm("mov.b64 %0, {%1, %1};" : "=l"(r) : "f"(x));
    return r;
}
__device__ __forceinline__ void fma2(unsigned long long& d, unsigned long long a,
                                     unsigned long long b) {
    asm("fma.rn.f32x2 %0, %1, %2, %0;" : "+l"(d) : "l"(a), "l"(b));
}
__device__ __forceinline__ float2 unpack2(unsigned long long v) {
    float2 f;
    asm("mov.b64 {%0, %1}, %2;" : "=f"(f.x), "=f"(f.y) : "l"(v));
    return f;
}

// ---------------- base-ISA helpers ----------------
__device__ __forceinline__ uint32_t smem_u32(const void* p) {
    uint32_t a;
    asm("{ .reg .u64 t; cvta.to.shared.u64 t, %1; cvt.u32.u64 %0, t; }" : "=r"(a) : "l"(p));
    return a;
}
__device__ __forceinline__ void cp16(uint32_t dst, const void* src) {
    asm volatile("cp.async.cg.shared.global [%0], [%1], 16;" :: "r"(dst), "l"(src));
}
#define LDSM_X4(r0, r1, r2, r3, addr) \
    asm volatile("ldmatrix.sync.aligned.m8n8.x4.shared.b16 {%0,%1,%2,%3}, [%4];" \
        : "=r"(r0), "=r"(r1), "=r"(r2), "=r"(r3) : "r"(addr))
__device__ __forceinline__ void mma16816(float* c, uint32_t a0, uint32_t a1, uint32_t a2,
                                         uint32_t a3, uint32_t b0, uint32_t b1) {
    asm volatile(
        "mma.sync.aligned.m16n8k16.row.col.f32.bf16.bf16.f32 "
        "{%0,%1,%2,%3}, {%4,%5,%6,%7}, {%8,%9}, {%0,%1,%2,%3};"
        : "+f"(c[0]), "+f"(c[1]), "+f"(c[2]), "+f"(c[3])
        : "r"(a0), "r"(a1), "r"(a2), "r"(a3), "r"(b0), "r"(b1));
}

// ---------------- bf16 split helpers ----------------
__device__ __forceinline__ uint32_t bfpair(float a, float b) {
    __nv_bfloat162 t = __floats2bfloat162_rn(a, b);
    return *reinterpret_cast<uint32_t*>(&t);
}
__device__ __forceinline__ float flo(float a) {
    return a - __bfloat162float(__float2bfloat16_rn(a));
}

// ---------------- weight folding kernels ----------------
__global__ void k_fold_u(const float* __restrict__ qw, const float* __restrict__ qb,
                         const float* __restrict__ kvw, const float* __restrict__ kvb,
                         const float* __restrict__ osw, const float* __restrict__ osb,
                         const float* __restrict__ saw, const float* __restrict__ sab,
                         const float* __restrict__ ssw, const float* __restrict__ ssb) {
    int i = threadIdx.x;
    float a = 0.f, b = 0.f, c = 0.f, d = 0.f;
    for (int h = 0; h < 256; h++) {
        a += qw[h * 256 + i] * osw[h];
        b += kvw[h * 256 + i] * osw[256 + h];
        c += saw[h * 256 + i] * ssw[h];
        d += saw[(256 + h) * 256 + i] * ssw[256 + h];
    }
    g_u[0][i] = a; g_u[1][i] = b; g_u[2][i] = c; g_u[3][i] = d;
    if (i == 0) {
        float C1 = osb[0], C2 = ssb[0];
        for (int h = 0; h < 256; h++) {
            C1 += qb[h] * osw[h] + kvb[h] * osw[256 + h];
            C2 += sab[h] * ssw[h] + sab[256 + h] * ssw[256 + h];
        }
        g_C[0] = C1; g_C[1] = C2;
    }
}

__global__ void k_fold_A(const float* __restrict__ ow, const float* __restrict__ sow,
                         const float* __restrict__ mixw) {
    int j = blockIdx.x, y = blockIdx.y, h = threadIdx.x;
    const float* W = y ? sow : ow;
    const float* mrow = mixw + j * 512 + y * 256;
    float s = 0.f;
    for (int d = 0; d < 256; d++) s += W[d * 256 + h] * mrow[d];
    (y ? g_A2 : g_A1)[h * 256 + j] = s;
}

__global__ void k_fold_M(const float* __restrict__ kvw, const float* __restrict__ kvb,
                         const float* __restrict__ saw, const float* __restrict__ sab,
                         const float* __restrict__ ob1, const float* __restrict__ ob2,
                         const float* __restrict__ mixw) {
    int j = blockIdx.x, y = blockIdx.y, i = threadIdx.x;
    const float* W = y ? (saw + 512 * 256) : (kvw + 256 * 256);
    const float* A = y ? g_A2 : g_A1;
    const float* bb = y ? (sab + 512) : (kvb + 256);
    const float* ob = y ? ob2 : ob1;
    float s = 0.f;
    for (int h = 0; h < 256; h++) s += W[h * 256 + i] * A[h * 256 + j];
    (y ? g_M2 : g_M1)[i * 256 + j] = s;

    __shared__ float red[256];
    red[i] = bb[i] * A[i * 256 + j] + ob[i] * mixw[j * 512 + y * 256 + i];
    __syncthreads();
    for (int st = 128; st > 0; st >>= 1) {
        if (i < st) red[i] += red[i + st];
        __syncthreads();
    }
    if (i == 0) g_cpart[y][j] = red[0];
}

__global__ void k_sqk(const float* __restrict__ opf, const float* __restrict__ mf) {
    int y = blockIdx.y;
    int row = blockIdx.x * 8 + (threadIdx.x >> 5);
    int l = threadIdx.x & 31;
    const float* X = (y == 1) ? opf : mf;
    const float* u = g_u[y];
    const float* xr = X + (size_t)row * 256;
    float s = 0.f;
#pragma unroll
    for (int t = 0; t < 8; t++) s += xr[t * 32 + l] * u[t * 32 + l];
#pragma unroll
    for (int o = 16; o > 0; o >>= 1) s += __shfl_xor_sync(0xffffffffu, s, o);
    if (l == 0) {
        float add = (y == 0) ? g_C[0] : (y == 2) ? g_C[1] : 0.f;
        float* dst = (y == 0) ? g_sq1 : (y == 1) ? g_sk1 : (y == 2) ? g_sq2 : g_sk2;
        dst[row] = s + add;
    }
}

// V' = X @ M, then emit bf16 hi/lo swizzled tile images (row=j, col=c-local)
__global__ void __launch_bounds__(256, 2)
k_proj(const float* __restrict__ opf, const float* __restrict__ mf) {
    int y = blockIdx.y;
    const float* X = y ? mf : opf;
    const float* M = y ? g_M2 : g_M1;
    int r0 = blockIdx.x * 64;
    int j = threadIdx.x;
    __shared__ __align__(16) float Xt[32][68];
    __shared__ __align__(16) char tile[32768];

    unsigned long long acc[32];
#pragma unroll
    for (int p = 0; p < 32; p++) acc[p] = 0ull;

    for (int k0 = 0; k0 < 256; k0 += 32) {
        __syncthreads();
#pragma unroll
        for (int p = 0; p < 8; p++) {
            int idx = p * 256 + j;
            int k = idx & 31, r = idx >> 5;
            Xt[k][r] = X[(size_t)(r0 + r) * 256 + k0 + k];
        }
        __syncthreads();
#pragma unroll 4
        for (int k = 0; k < 32; k++) {
            float mv = __ldg(&M[(k0 + k) * 256 + j]);
            unsigned long long mp = pack2(mv);
            const ulonglong2* rowp = (const ulonglong2*)&Xt[k][0];
#pragma unroll
            for (int q = 0; q < 16; q++) {
                ulonglong2 ww = rowp[q];
                fma2(acc[2 * q], ww.x, mp);
                fma2(acc[2 * q + 1], ww.y, mp);
            }
        }
    }

    // emit tiles: this block covers exactly one (b, chunk): 64 c x 256 j
    int bb = r0 >> 11, chk = (r0 & 2047) >> 6;
    size_t tb = (size_t)((y * 8 + bb) * 32 + chk) * 32768;
    int pj = j & 7;
#pragma unroll
    for (int rd = 0; rd < 2; rd++) {
        __syncthreads();
        char* trow = tile + j * 128;
#pragma unroll
        for (int g = 0; g < 8; g++) {
            float2 v0 = unpack2(acc[4 * g + 0]);
            float2 v1 = unpack2(acc[4 * g + 1]);
            float2 v2 = unpack2(acc[4 * g + 2]);
            float2 v3 = unpack2(acc[4 * g + 3]);
            uint4 W;
            if (rd == 0) {
                W.x = bfpair(v0.x, v0.y); W.y = bfpair(v1.x, v1.y);
                W.z = bfpair(v2.x, v2.y); W.w = bfpair(v3.x, v3.y);
            } else {
                W.x = bfpair(flo(v0.x), flo(v0.y)); W.y = bfpair(flo(v1.x), flo(v1.y));
                W.z = bfpair(flo(v2.x), flo(v2.y)); W.w = bfpair(flo(v3.x), flo(v3.y));
            }
            *(uint4*)(trow + ((g ^ pj) * 16)) = W;
        }
        __syncthreads();
        uint4* dt = (uint4*)((rd ? g_Blo : g_Bhi) + tb);
        const uint4* st = (const uint4*)tile;
#pragma unroll
        for (int q = 0; q < 8; q++) dt[j + 256 * q] = st[j + 256 * q];
    }
}

// ---------------- mma.sync fused attention pass ----------------
// smem layout (bytes)
#define OF_PH(s) ((s) * 32768)
#define OF_PL(s) ((s) * 32768 + 16384)
#define OF_VH(s) (65536 + (s) * 65536)
#define OF_VL(s) (65536 + (s) * 65536 + 32768)
#define OF_DEN 196608
#define OF_SDI 198656
#define OF_SQS 199168
#define OF_CV  199680
#define SMEM_SZ 200704

__device__ __forceinline__ float pexp(float sq, float sk, float mk) {
    float s = sq + sk;
    s = fmaxf(s, 0.01f * s);
    return __expf(s * mk);
}

template <int PASS>
__global__ void __launch_bounds__(512, 1)
k_attn(const float* __restrict__ mask, const float* __restrict__ mixb,
       float* __restrict__ out) {
    extern __shared__ __align__(1024) char sm[];
    const uint32_t smb = smem_u32(sm);
    const int tid = threadIdx.x;
    const int b = blockIdx.y, m0 = blockIdx.x * 128;

    const float* sqsrc = (PASS ? g_sq2 : g_sq1) + b * Nn + m0;
    if (tid < 128) ((float*)(sm + OF_SQS))[tid] = sqsrc[tid];
    if (PASS == 0 && tid < 256)
        ((float*)(sm + OF_CV))[tid] = g_cpart[0][tid] + g_cpart[1][tid] + mixb[tid];
    __syncthreads();

    // ---- P-gen mapping: thread covers (row pm, c-quarter pch: 16 c) ----
    const int pm = tid >> 2, pch = tid & 3;
    const int pm7 = pm & 7;
    const float sqm = ((const float*)(sm + OF_SQS))[pm];
    const float* mrow = mask + ((size_t)(b * Nn + m0 + pm)) * Nn + pch * 16;
    const float* skb = (PASS ? g_sk2 : g_sk1) + b * Nn + pch * 16;
    const char* srcH = g_Bhi + (size_t)((PASS * 8 + b) * 32) * 32768;
    const char* srcL = g_Blo + (size_t)((PASS * 8 + b) * 32) * 32768;
    float den_local = 0.f;

    // ---- MMA mapping: warp wid owns C rows [wm*16, wm*16+16), cols [wn*128, +128) ----
    const int l = tid & 31, wid = tid >> 5;
    const int wm = wid >> 1, wn = wid & 1;
    const int rA = wm * 16 + (l & 15);
    const int gA = (l >> 4) & 1;
    const uint32_t aRowOff = (uint32_t)rA * 128;
    const int rA7 = rA & 7;
    const int rBl = (l & 7) + ((l & 16) ? 8 : 0);
    const int gB = (l >> 3) & 1;
    const int l7 = l & 7;
    const uint32_t bRowBase = (uint32_t)(wn * 128 + rBl) * 128;

    float acc[16][4];
#pragma unroll
    for (int f = 0; f < 16; f++) {
        acc[f][0] = 0.f; acc[f][1] = 0.f; acc[f][2] = 0.f; acc[f][3] = 0.f;
    }

    auto mma_chunk = [&](int t) {
        const uint32_t phb = smb + OF_PH(t) + aRowOff;
        const uint32_t plb = smb + OF_PL(t) + aRowOff;
        const uint32_t vhb = smb + OF_VH(t) + bRowBase;
        const uint32_t vlb = smb + OF_VL(t) + bRowBase;
#pragma unroll
        for (int ks = 0; ks < 4; ks++) {
            const uint32_t aswz = (uint32_t)(((ks * 2 + gA) ^ rA7) * 16);
            const uint32_t bswz = (uint32_t)(((ks * 2 + gB) ^ l7) * 16);
            uint32_t ah0, ah1, ah2, ah3, al0, al1, al2, al3;
            LDSM_X4(ah0, ah1, ah2, ah3, phb + aswz);
            LDSM_X4(al0, al1, al2, al3, plb + aswz);
#pragma unroll
            for (int f2 = 0; f2 < 8; f2++) {
                uint32_t boff = bswz + (uint32_t)f2 * 2048;
                uint32_t bh0, bh1, bh2, bh3, bl0, bl1, bl2, bl3;
                LDSM_X4(bh0, bh1, bh2, bh3, vhb + boff);
                LDSM_X4(bl0, bl1, bl2, bl3, vlb + boff);
                float* cA = acc[f2 * 2];
                float* cB = acc[f2 * 2 + 1];
                mma16816(cA, ah0, ah1, ah2, ah3, bh0, bh1);
                mma16816(cA, ah0, ah1, ah2, ah3, bl0, bl1);
                mma16816(cA, al0, al1, al2, al3, bh0, bh1);
                mma16816(cB, ah0, ah1, ah2, ah3, bh2, bh3);
                mma16816(cB, ah0, ah1, ah2, ah3, bl2, bl3);
                mma16816(cB, al0, al1, al2, al3, bh2, bh3);
            }
        }
    };

    for (int i = 0; i < 32; i++) {
        const int s = i & 1;
        // ---- V tiles: linear cp.async copies (pre-swizzled in global) ----
        {
            uint32_t dh = smb + OF_VH(s) + tid * 64;
            uint32_t dl = smb + OF_VL(s) + tid * 64;
            const char* sh = srcH + (size_t)i * 32768 + tid * 64;
            const char* sl = srcL + (size_t)i * 32768 + tid * 64;
#pragma unroll
            for (int q = 0; q < 4; q++) {
                cp16(dh + q * 16, sh + q * 16);
                cp16(dl + q * 16, sl + q * 16);
            }
        }
        asm volatile("cp.async.commit_group;" ::: "memory");
        // ---- P tile: 16 c values for (pm, pch), bf16 hi/lo, swizzled ----
        {
            const float4* mp = (const float4*)(mrow + (size_t)i * 64);
            const float4* kp = (const float4*)(skb + i * 64);
            float e[16];
#pragma unroll
            for (int q = 0; q < 4; q++) {
                float4 mk = __ldg(mp + q);
                float4 sv = kp[q];
                e[4 * q + 0] = pexp(sqm, sv.x, mk.x);
                e[4 * q + 1] = pexp(sqm, sv.y, mk.y);
                e[4 * q + 2] = pexp(sqm, sv.z, mk.z);
                e[4 * q + 3] = pexp(sqm, sv.w, mk.w);
            }
#pragma unroll
            for (int q = 0; q < 16; q++) den_local += e[q];
            uint4 H0, H1, L0, L1;
            H0.x = bfpair(e[0], e[1]);   H0.y = bfpair(e[2], e[3]);
            H0.z = bfpair(e[4], e[5]);   H0.w = bfpair(e[6], e[7]);
            H1.x = bfpair(e[8], e[9]);   H1.y = bfpair(e[10], e[11]);
            H1.z = bfpair(e[12], e[13]); H1.w = bfpair(e[14], e[15]);
            L0.x = bfpair(flo(e[0]), flo(e[1]));   L0.y = bfpair(flo(e[2]), flo(e[3]));
            L0.z = bfpair(flo(e[4]), flo(e[5]));   L0.w = bfpair(flo(e[6]), flo(e[7]));
            L1.x = bfpair(flo(e[8]), flo(e[9]));   L1.y = bfpair(flo(e[10]), flo(e[11]));
            L1.z = bfpair(flo(e[12]), flo(e[13])); L1.w = bfpair(flo(e[14]), flo(e[15]));
            char* ph = sm + OF_PH(s) + pm * 128;
            char* pl = sm + OF_PL(s) + pm * 128;
            int o0 = ((2 * pch) ^ pm7) * 16;
            int o1 = ((2 * pch + 1) ^ pm7) * 16;
            *(uint4*)(ph + o0) = H0;
            *(uint4*)(ph + o1) = H1;
            *(uint4*)(pl + o0) = L0;
            *(uint4*)(pl + o1) = L1;
        }
        if (i > 0) mma_chunk(s ^ 1);
        asm volatile("cp.async.wait_group 0;" ::: "memory");
        __syncthreads();
    }
    mma_chunk(1);

    // ---- denominators ----
    ((float*)(sm + OF_DEN))[tid] = den_local;
    __syncthreads();
    if (tid < 128) {
        const float* dd = (const float*)(sm + OF_DEN) + tid * 4;
        ((float*)(sm + OF_SDI))[tid] = 1.0f / ((dd[0] + dd[1]) + (dd[2] + dd[3]));
    }
    __syncthreads();

    const float* sdi = (const float*)(sm + OF_SDI);
    const float* cvp = (const float*)(sm + OF_CV);
    const int r0l = wm * 16 + (l >> 2);
    const float inv0 = sdi[r0l], inv1 = sdi[r0l + 8];
    float* o0 = out + ((size_t)(b * Nn + m0 + r0l)) * 256 + wn * 128 + 2 * (l & 3);
    float* o1 = o0 + 8 * 256;
#pragma unroll
    for (int f = 0; f < 16; f++) {
        int col = wn * 128 + f * 8 + 2 * (l & 3);
        float2 v0, v1;
        v0.x = acc[f][0] * inv0; v0.y = acc[f][1] * inv0;
        v1.x = acc[f][2] * inv1; v1.y = acc[f][3] * inv1;
        if (PASS == 0) {
            float c0 = cvp[col], c1 = cvp[col + 1];
            v0.x += c0; v0.y += c1; v1.x += c0; v1.y += c1;
        } else {
            float2 p0 = *(float2*)(o0 + f * 8);
            float2 p1 = *(float2*)(o1 + f * 8);
            v0.x += p0.x; v0.y += p0.y; v1.x += p1.x; v1.y += p1.y;
        }
        *(float2*)(o0 + f * 8) = v0;
        *(float2*)(o1 + f * 8) = v1;
    }
}

// ---------------- launch ----------------
extern "C" void kernel_launch(void* const* d_in, const int* in_sizes, int n_in,
                              void* d_out, int out_size) {
    const float* opf   = (const float*)d_in[0];
    const float* mf    = (const float*)d_in[1];
    const float* tmask = (const float*)d_in[2];
    const float* smask = (const float*)d_in[3];
    const float* qw  = (const float*)d_in[4];
    const float* qb  = (const float*)d_in[5];
    const float* kvw = (const float*)d_in[6];
    const float* kvb = (const float*)d_in[7];
    const float* osw = (const float*)d_in[8];
    const float* osb = (const float*)d_in[9];
    const float* ow  = (const float*)d_in[10];
    const float* ob  = (const float*)d_in[11];
    const float* saw = (const float*)d_in[12];
    const float* sab = (const float*)d_in[13];
    const float* ssw = (const float*)d_in[14];
    const float* ssb = (const float*)d_in[15];
    const float* sow = (const float*)d_in[16];
    const float* sob = (const float*)d_in[17];
    const float* mixw = (const float*)d_in[18];
    const float* mixb = (const float*)d_in[19];
    float* out = (float*)d_out;

    cudaFuncSetAttribute(k_attn<0>, cudaFuncAttributeMaxDynamicSharedMemorySize, SMEM_SZ);
    cudaFuncSetAttribute(k_attn<1>, cudaFuncAttributeMaxDynamicSharedMemorySize, SMEM_SZ);

    k_fold_u<<<1, 256>>>(qw, qb, kvw, kvb, osw, osb, saw, sab, ssw, ssb);
    k_fold_A<<<dim3(256, 2), 256>>>(ow, sow, mixw);
    k_fold_M<<<dim3(256, 2), 256>>>(kvw, kvb, saw, sab, ob, sob, mixw);
    k_sqk<<<dim3(2048, 4), 256>>>(opf, mf);
    k_proj<<<dim3(256, 2), 256>>>(opf, mf);
    k_attn<0><<<dim3(16, 8), 512, SMEM_SZ>>>(tmask, mixb, out);
    k_attn<1><<<dim3(16, 8), 512, SMEM_SZ>>>(smask, mixb, out);
}